// round 14
// baseline (speedup 1.0000x reference)
#include <cuda_runtime.h>
#include <cuda_bf16.h>
#include <cstdint>

// CRFConstituency inside-outside, B=8, S=256, lens==255 (fixed triu mask).
// R14 = R13 (halo blocking MW=8, 8-CTA cluster/batch, full smem replica,
// s32-redux warp max, early-break chunk loops) with the backward inner loops
// restructured into the forward's two-phase pattern:
//   phase 1: tv[c] = s_tri[..] + __ldcg(A[..])  (8 independent LDS+LDG in
//            flight -> L2 latency amortized by MLP instead of serialized)
//   phase 2: acc += __expf(s_ab + tv[c])
// Previously each iteration chained LDG(234cyc)->FADD->MUFU->acc serially.

#define SS 256
#define BB 8
#define CLUSTER 8
#define NTHREADS 1024
#define MW 8
#define TRI ((SS*(SS-1))/2)          // 32640 floats
#define SMEM_BYTES (TRI*4)           // 130560 bytes dynamic
#define NEGF (-1e30f)

__device__ float g_Ar[BB][SS][SS];
__device__ float g_Ac[BB][SS][SS];

__device__ __forceinline__ int tri_base(int i) {
    return i * (SS - 1) - ((i * (i - 1)) >> 1);
}

__device__ __forceinline__ uint32_t smem_u32(const void* p) {
    uint32_t a;
    asm("{ .reg .u64 t; cvta.to.shared.u64 t, %1; cvt.u32.u64 %0, t; }"
        : "=r"(a) : "l"(p));
    return a;
}

__device__ __forceinline__ void st_peer(uint32_t local_addr, int peer, float v) {
    uint32_t rem;
    asm volatile("mapa.shared::cluster.u32 %0, %1, %2;"
                 : "=r"(rem) : "r"(local_addr), "r"(peer));
    asm volatile("st.shared::cluster.f32 [%0], %1;" :: "r"(rem), "f"(v));
}

__device__ __forceinline__ void cluster_sync_all() {
    asm volatile("barrier.cluster.arrive.aligned;" ::: "memory");
    asm volatile("barrier.cluster.wait.aligned;" ::: "memory");
}

// warp-wide fp32 max via integer redux (monotone embedding; finite values only)
__device__ __forceinline__ float warp_max_f32(float v) {
    int i = __float_as_int(v);
    i = (i >= 0) ? i : (i ^ 0x7fffffff);
    int r;
    asm volatile("redux.sync.max.s32 %0, %1, 0xffffffff;" : "=r"(r) : "r"(i));
    r = (r >= 0) ? r : (r ^ 0x7fffffff);
    return __int_as_float(r);
}

__device__ __forceinline__ float warp_sum_f32(float v) {
    #pragma unroll
    for (int o = 16; o; o >>= 1)
        v += __shfl_xor_sync(0xffffffffu, v, o);
    return v;
}

__global__ __launch_bounds__(NTHREADS, 1) __cluster_dims__(CLUSTER, 1, 1)
void crf_inside_outside_halo(const float* __restrict__ scores,
                             float* __restrict__ out)
{
    extern __shared__ float s_tri[];     // full packed triangle replica

    const int b = blockIdx.x >> 3;       // cluster index = batch
    uint32_t rank;
    asm("mov.u32 %0, %%cluster_ctarank;" : "=r"(rank));

    const float* sc = scores + b * SS * SS;
    float* mout     = out    + b * SS * SS;

    const int tid  = threadIdx.x;
    const int lane = tid & 31;
    const int wid  = tid >> 5;           // 32 warps
    const int base = (int)rank << 5;     // owned span starts [base, base+32)

    // ---------------- forward width-1 init (local replica) ----------------
    for (int i = tid; i < SS - 1; i += NTHREADS)
        s_tri[tri_base(i)] = sc[i * SS + i + 1];
    __syncthreads();
    cluster_sync_all();

    // ---------------- forward widths 2..255 in blocks of MW ----------------
    for (int w0 = 2; w0 <= SS - 1; w0 += MW) {
        const int wtop = (w0 + MW - 1 < SS - 1) ? (w0 + MW - 1) : (SS - 1);

        for (int w = w0; w <= wtop; ++w) {
            const int hal = wtop - w;                 // halo width this sub-step
            const int hi0 = base + 32 + hal;
            const int hi  = (hi0 < SS - w) ? hi0 : (SS - w);
            const int nch = (w - 1 + 31) >> 5;

            for (int i = base + wid; i < hi; i += 32) {
                const int j = i + w;
                const int rb_i = tri_base(i);
                const float scij = __ldca(&sc[i * SS + j]);

                int k0   = i + 1 + lane;
                int off1 = rb_i + lane;
                int off2 = tri_base(k0) + (j - k0 - 1);
                int kk   = k0;

                float tv[8];
                float mx = NEGF;
                #pragma unroll
                for (int c = 0; c < 8; ++c) {
                    if (c >= nch) break;
                    tv[c] = (kk < j) ? (s_tri[off1] + s_tri[off2]) : NEGF;
                    mx = fmaxf(mx, tv[c]);
                    off1 += 32;
                    off2 += 7632 - (kk << 5);
                    kk   += 32;
                }
                mx = warp_max_f32(mx);

                float acc = 0.f;
                #pragma unroll
                for (int c = 0; c < 8; ++c) {
                    if (c >= nch) break;
                    acc += __expf(tv[c] - mx);
                }
                acc = warp_sum_f32(acc);

                if (lane == 0)
                    s_tri[rb_i + (w - 1)] = scij + mx + __logf(acc);
            }
            __syncthreads();
        }

        // broadcast owned spans of widths w0..wtop to the 7 peer replicas
        const int wcnt = wtop - w0 + 1;
        for (int idx = tid; idx < wcnt * 32; idx += NTHREADS) {
            const int t = idx >> 5;
            const int i = base + (idx & 31);
            const int w = w0 + t;
            if (i < SS - w) {
                const int off = tri_base(i) + (w - 1);
                const float val = s_tri[off];
                const uint32_t laddr = smem_u32(&s_tri[off]);
                #pragma unroll
                for (int p = 0; p < CLUSTER; ++p)
                    if (p != (int)rank) st_peer(laddr, p, val);
            }
        }
        cluster_sync_all();
    }

    // ---------------- backward init ----------------
    for (int idx = ((int)rank << 13) + tid; idx < (((int)rank + 1) << 13); idx += NTHREADS) {
        const int i = idx >> 8;
        const int j = idx & 255;
        if (j <= i) mout[idx] = 0.f;
    }
    if (rank == 0 && tid == 0) {
        const float s_top = s_tri[tri_base(0) + (SS - 2)];
        mout[SS - 1] = 1.0f;
        const float A = sc[SS - 1] - s_top;      // log g = 0
        __stcg(&g_Ar[b][0][SS - 1], A);
        __stcg(&g_Ac[b][SS - 1][0], A);
    }
    cluster_sync_all();

    // ---------------- backward widths 254..1 in blocks of MW ----------------
    // g[a,bc] = sum_{j>bc} exp(s_ab + s[bc,j] + Ar[a][j])
    //         + sum_{i<a}  exp(s_ab + s[i,a]  + Ac[bc][i])
    for (int w0 = SS - 2; w0 >= 1; w0 -= MW) {
        const int wbot = (w0 - MW + 1 > 1) ? (w0 - MW + 1) : 1;

        for (int w = w0; w >= wbot; --w) {
            const int hal = w - wbot;                 // halo width this sub-step
            const int lo0 = base - hal;
            const int lo  = (lo0 > 0) ? lo0 : 0;
            const int hi0 = base + 32;
            const int hi  = (hi0 < SS - w) ? hi0 : (SS - w);

            for (int a = lo + wid; a < hi; a += 32) {
                const int bc = a + w;
                const float s_ab = s_tri[tri_base(a) + (w - 1)];
                const float scab = __ldca(&sc[a * SS + bc]);

                float acc = 0.f;

                // segment 1: parents (a, j), j = bc+1 .. S-1  (two-phase)
                {
                    const int n1 = SS - 1 - bc;
                    const int c1 = (n1 + 31) >> 5;
                    const int rb_bc = tri_base(bc);
                    const float* Ar = &g_Ar[b][a][0];

                    float tv[8];
                    int j = bc + 1 + lane;
                    #pragma unroll
                    for (int c = 0; c < 8; ++c) {
                        if (c >= c1) break;
                        tv[c] = (j < SS) ? (s_tri[rb_bc + (j - bc - 1)] + __ldcg(Ar + j))
                                         : NEGF;
                        j += 32;
                    }
                    #pragma unroll
                    for (int c = 0; c < 8; ++c) {
                        if (c >= c1) break;
                        acc += __expf(s_ab + tv[c]);
                    }
                }
                // segment 2: parents (i, bc), i = 0 .. a-1  (two-phase)
                {
                    const int c2 = (a + 31) >> 5;
                    const float* Ac = &g_Ac[b][bc][0];

                    float tv[8];
                    int i   = lane;
                    int off = tri_base(lane) + (a - lane - 1);
                    #pragma unroll
                    for (int c = 0; c < 8; ++c) {
                        if (c >= c2) break;
                        tv[c] = (i < a) ? (s_tri[off] + __ldcg(Ac + i)) : NEGF;
                        off += 7632 - (i << 5);
                        i   += 32;
                    }
                    #pragma unroll
                    for (int c = 0; c < 8; ++c) {
                        if (c >= c2) break;
                        acc += __expf(s_ab + tv[c]);
                    }
                }

                acc = warp_sum_f32(acc);

                if (lane == 0) {
                    const float g = acc;
                    mout[a * SS + bc] = g;
                    const float A = __logf(g) + scab - s_ab;
                    __stcg(&g_Ar[b][a][bc], A);
                    __stcg(&g_Ac[b][bc][a], A);
                }
            }
            __syncthreads();
        }
        cluster_sync_all();
    }
}

extern "C" void kernel_launch(void* const* d_in, const int* in_sizes, int n_in,
                              void* d_out, int out_size)
{
    (void)in_sizes; (void)n_in; (void)out_size;
    const float* scores = (const float*)d_in[0];
    float* out = (float*)d_out;

    cudaFuncSetAttribute(crf_inside_outside_halo,
                         cudaFuncAttributeMaxDynamicSharedMemorySize, SMEM_BYTES);
    crf_inside_outside_halo<<<BB * CLUSTER, NTHREADS, SMEM_BYTES>>>(scores, out);
}

// round 15
// speedup vs baseline: 1.3026x; 1.3026x over previous
#include <cuda_runtime.h>
#include <cuda_bf16.h>
#include <cstdint>

// CRFConstituency inside-outside, B=8, S=256, lens==255 (fixed triu mask).
// R15: blocked (tiled) CYK. 8-CTA cluster per batch; CTA r owns tile rows
// starting at 32r. Triangle split into 32x32 tiles T(I,J).
// Forward, per tile diagonal d = J-I:
//   GEMM phase: contributions from k-blocks strictly between I and J —
//     log-semiring "GEMM" over finished tiles, warp-per-entry, no deps.
//   Closure phase: k in block I / block J terms, swept over 63 sub-diagonals
//     (<=2 chunks per entry), CTA-local __syncthreads only.
//   Then broadcast the tile to all peer replicas + one barrier.cluster.
// Backward mirrors it in reverse tile-diagonal order: GEMM over global A
// (plain sums — every term <= marginal <= 1, no overflow), closure with the
// A tile staged in padded smem, then A written to g_Ar/g_Ac for later tiles.
// Cluster-wide syncs: 128 -> 16. Critical-path sub-steps each shrink from
// up-to-8-chunk LSEs to <=2 chunks.

#define SS 256
#define BB 8
#define CLUSTER 8
#define NTHREADS 1024
#define TRI ((SS*(SS-1))/2)          // 32640 floats
#define SMEM_BYTES (TRI*4)           // 130560 bytes dynamic
#define NEGF (-1e30f)

__device__ float g_Ar[BB][SS][SS];
__device__ float g_Ac[BB][SS][SS];

__device__ __forceinline__ int tri_base(int i) {
    return i * (SS - 1) - ((i * (i - 1)) >> 1);
}

__device__ __forceinline__ uint32_t smem_u32(const void* p) {
    uint32_t a;
    asm("{ .reg .u64 t; cvta.to.shared.u64 t, %1; cvt.u32.u64 %0, t; }"
        : "=r"(a) : "l"(p));
    return a;
}

__device__ __forceinline__ void st_peer(uint32_t local_addr, int peer, float v) {
    uint32_t rem;
    asm volatile("mapa.shared::cluster.u32 %0, %1, %2;"
                 : "=r"(rem) : "r"(local_addr), "r"(peer));
    asm volatile("st.shared::cluster.f32 [%0], %1;" :: "r"(rem), "f"(v));
}

__device__ __forceinline__ void cluster_sync_all() {
    asm volatile("barrier.cluster.arrive.aligned;" ::: "memory");
    asm volatile("barrier.cluster.wait.aligned;" ::: "memory");
}

// warp-wide fp32 max via integer redux (monotone embedding; finite values only)
__device__ __forceinline__ float warp_max_f32(float v) {
    int i = __float_as_int(v);
    i = (i >= 0) ? i : (i ^ 0x7fffffff);
    int r;
    asm volatile("redux.sync.max.s32 %0, %1, 0xffffffff;" : "=r"(r) : "r"(i));
    r = (r >= 0) ? r : (r ^ 0x7fffffff);
    return __int_as_float(r);
}

__device__ __forceinline__ float warp_sum_f32(float v) {
    #pragma unroll
    for (int o = 16; o; o >>= 1)
        v += __shfl_xor_sync(0xffffffffu, v, o);
    return v;
}

__global__ __launch_bounds__(NTHREADS, 1) __cluster_dims__(CLUSTER, 1, 1)
void crf_inside_outside_tiled(const float* __restrict__ scores,
                              float* __restrict__ out)
{
    extern __shared__ float s_tri[];            // packed triangle replica
    __shared__ float sm_m[1024];                // forward GEMM partial max
    __shared__ float sm_s[1024];                // GEMM partial sum (fwd+bwd)
    __shared__ float a_tile[32 * 33];           // backward A tile (padded)

    const int b = blockIdx.x >> 3;
    uint32_t rank;
    asm("mov.u32 %0, %%cluster_ctarank;" : "=r"(rank));
    const int R = (int)rank;

    const float* sc = scores + b * SS * SS;
    float* mout     = out    + b * SS * SS;

    const int tid  = threadIdx.x;
    const int lane = tid & 31;
    const int wid  = tid >> 5;                  // 32 warps

    // ---------------- width-1 init (every CTA fills its own replica) -------
    for (int i = tid; i < SS - 1; i += NTHREADS)
        s_tri[tri_base(i)] = sc[i * SS + i + 1];
    __syncthreads();

    // ================= FORWARD =================
    // F0: diagonal tile (R,R): widths 2..31, all deps block-local.
    for (int w = 2; w <= 31; ++w) {
        if (wid < 32 - w) {
            const int i = 32 * R + wid;
            const int j = i + w;
            float tv = NEGF;
            if (lane < w - 1) {
                const int k = i + 1 + lane;
                tv = s_tri[tri_base(i) + lane] + s_tri[tri_base(k) + (j - k - 1)];
            }
            const float mx = warp_max_f32(tv);
            float e = (lane < w - 1) ? __expf(tv - mx) : 0.f;
            e = warp_sum_f32(e);
            if (lane == 0)
                s_tri[tri_base(i) + (w - 1)] =
                    __ldca(&sc[i * SS + j]) + mx + __logf(e);
        }
        __syncthreads();
    }
    // broadcast tile (R,R) (incl. width-1 entries; peers have those already,
    // rewriting the identical value is benign)
    for (int e = tid; e < 1024; e += NTHREADS) {
        const int ti = e >> 5, tj = e & 31;
        if (tj > ti) {
            const int i = 32 * R + ti, j = 32 * R + tj;
            const int off = tri_base(i) + (j - i - 1);
            const float v = s_tri[off];
            const uint32_t la = smem_u32(&s_tri[off]);
            #pragma unroll
            for (int p = 0; p < CLUSTER; ++p)
                if (p != R) st_peer(la, p, v);
        }
    }
    cluster_sync_all();

    // F_d: d = 1..7, CTA R handles tile (R, R+d)
    for (int d = 1; d <= 7; ++d) {
        const int J = R + d;
        if (J <= 7) {
            // ---- GEMM phase: warp = tile row ti = wid ----
            {
                const int i = 32 * R + wid;
                const int rb_i = tri_base(i);
                for (int tj = 0; tj < 32; ++tj) {
                    const int j = 32 * J + tj;
                    float tv[6];
                    float mx = NEGF;
                    #pragma unroll
                    for (int c = 0; c < 6; ++c) {
                        if (c >= d - 1) break;
                        const int k = 32 * (R + 1 + c) + lane;
                        tv[c] = s_tri[rb_i + (k - i - 1)] +
                                s_tri[tri_base(k) + (j - k - 1)];
                        mx = fmaxf(mx, tv[c]);
                    }
                    mx = warp_max_f32(mx);
                    float sm = 0.f;
                    #pragma unroll
                    for (int c = 0; c < 6; ++c) {
                        if (c >= d - 1) break;
                        sm += __expf(tv[c] - mx);
                    }
                    sm = warp_sum_f32(sm);
                    if (lane == 0) {
                        sm_m[wid * 32 + tj] = mx;
                        sm_s[wid * 32 + tj] = sm;
                    }
                }
            }
            __syncthreads();
            // ---- closure: sub-diagonals t = -31..31 ----
            for (int t = -31; t <= 31; ++t) {
                const int cnt = 32 - (t < 0 ? -t : t);
                if (wid < cnt) {
                    const int ti = (t < 0 ? -t : 0) + wid;
                    const int tj = ti + t;
                    const int i = 32 * R + ti, j = 32 * J + tj;
                    const int w = j - i;
                    const float scij = __ldca(&sc[i * SS + j]);
                    float val;
                    if (w == 1) {
                        val = scij;                 // d==1, (31,0): no inner k
                    } else {
                        const float m0 = sm_m[ti * 32 + tj];
                        const float s0 = sm_s[ti * 32 + tj];
                        float tvA = NEGF, tvB = NEGF;
                        if (lane > ti) {            // k in block R
                            const int k = 32 * R + lane;
                            tvA = s_tri[tri_base(i) + (k - i - 1)] +
                                  s_tri[tri_base(k) + (j - k - 1)];
                        }
                        if (lane < tj) {            // k in block J
                            const int k = 32 * J + lane;
                            tvB = s_tri[tri_base(i) + (k - i - 1)] +
                                  s_tri[tri_base(k) + (j - k - 1)];
                        }
                        float m1 = warp_max_f32(fmaxf(tvA, tvB));
                        const float m = fmaxf(m0, m1);
                        float sm = __expf(tvA - m) + __expf(tvB - m); // NEGF->0
                        if (lane == 0) sm += s0 * __expf(m0 - m);
                        sm = warp_sum_f32(sm);
                        val = scij + m + __logf(sm);
                    }
                    if (lane == 0)
                        s_tri[tri_base(i) + (w - 1)] = val;
                }
                __syncthreads();
            }
            // ---- broadcast tile (R,J) ----
            for (int e = tid; e < 1024; e += NTHREADS) {
                const int ti = e >> 5, tj = e & 31;
                const int i = 32 * R + ti, j = 32 * J + tj;
                const int off = tri_base(i) + (j - i - 1);
                const float v = s_tri[off];
                const uint32_t la = smem_u32(&s_tri[off]);
                #pragma unroll
                for (int p = 0; p < CLUSTER; ++p)
                    if (p != R) st_peer(la, p, v);
            }
        }
        cluster_sync_all();
    }

    // ================= BACKWARD =================
    // zero lower triangle + diagonal of output
    for (int idx = (R << 13) + tid; idx < ((R + 1) << 13); idx += NTHREADS) {
        const int i = idx >> 8, j = idx & 255;
        if (j <= i) mout[idx] = 0.f;
    }

    // tiles in decreasing diagonal d = 7..0; CTA R handles tile (R, R+d).
    for (int d = 7; d >= 0; --d) {
        const int C = R + d;
        if (C <= 7) {
            const int nch = 7 - d;              // (7-C) seg1 + R seg2 chunks
            // ---- GEMM phase over finished (wider) tiles: plain sums ----
            {
                const int a = 32 * R + wid;
                for (int tj = 0; tj < 32; ++tj) {
                    const int bc = 32 * C + tj;
                    if (a < bc) {
                        const float s_ab = s_tri[tri_base(a) + (bc - a - 1)];
                        float tv[7];
                        #pragma unroll
                        for (int c = 0; c < 7; ++c) {
                            if (c >= nch) break;
                            if (c < 7 - C) {    // parents (a, j), j-block > C
                                const int j = 32 * (C + 1 + c) + lane;
                                tv[c] = __ldcg(&g_Ar[b][a][j]) +
                                        s_tri[tri_base(bc) + (j - bc - 1)];
                            } else {            // parents (i, bc), i-block < R
                                const int i2 = 32 * (c - (7 - C)) + lane;
                                tv[c] = __ldcg(&g_Ac[b][bc][i2]) +
                                        s_tri[tri_base(i2) + (a - i2 - 1)];
                            }
                        }
                        float sm = 0.f;
                        #pragma unroll
                        for (int c = 0; c < 7; ++c) {
                            if (c >= nch) break;
                            sm += __expf(s_ab + tv[c]);
                        }
                        sm = warp_sum_f32(sm);
                        if (lane == 0) sm_s[wid * 32 + tj] = sm;
                    }
                }
            }
            __syncthreads();
            // ---- closure: sub-diagonals t = 31 .. (d?-31:1) ----
            const int tmin = (d == 0) ? 1 : -31;
            for (int t = 31; t >= tmin; --t) {
                const int cnt = 32 - (t < 0 ? -t : t);
                if (wid < cnt) {
                    const int ti = (t < 0 ? -t : 0) + wid;
                    const int tj = ti + t;
                    const int a = 32 * R + ti, bc = 32 * C + tj;
                    const float s_ab = s_tri[tri_base(a) + (bc - a - 1)];
                    const float scab = __ldca(&sc[a * SS + bc]);
                    float part = 0.f;
                    if (lane > tj) {            // parents (a, j), j in block C
                        const int j = 32 * C + lane;
                        part += __expf(s_ab + a_tile[ti * 33 + lane] +
                                       s_tri[tri_base(bc) + (j - bc - 1)]);
                    }
                    if (lane < ti) {            // parents (i, bc), i in block R
                        const int i2 = 32 * R + lane;
                        part += __expf(s_ab + a_tile[lane * 33 + tj] +
                                       s_tri[tri_base(i2) + (a - i2 - 1)]);
                    }
                    if (lane == 0) part += sm_s[ti * 32 + tj];
                    float g = warp_sum_f32(part);
                    if (a == 0 && bc == SS - 1) g = 1.0f;   // root seed
                    if (lane == 0) {
                        mout[a * SS + bc] = g;
                        a_tile[ti * 33 + tj] = __logf(g) + scab - s_ab;
                    }
                }
                __syncthreads();
            }
            // ---- publish A tile to global (both copies) ----
            for (int e = tid; e < 1024; e += NTHREADS) {
                const int ti = e >> 5, tj = e & 31;
                const int a = 32 * R + ti, bc = 32 * C + tj;
                if (a < bc) {
                    const float v = a_tile[ti * 33 + tj];
                    __stcg(&g_Ar[b][a][bc], v);
                    __stcg(&g_Ac[b][bc][a], v);
                }
            }
        }
        cluster_sync_all();
    }
}

extern "C" void kernel_launch(void* const* d_in, const int* in_sizes, int n_in,
                              void* d_out, int out_size)
{
    (void)in_sizes; (void)n_in; (void)out_size;
    const float* scores = (const float*)d_in[0];
    float* out = (float*)d_out;

    cudaFuncSetAttribute(crf_inside_outside_tiled,
                         cudaFuncAttributeMaxDynamicSharedMemorySize, SMEM_BYTES);
    crf_inside_outside_tiled<<<BB * CLUSTER, NTHREADS, SMEM_BYTES>>>(scores, out);
}